// round 3
// baseline (speedup 1.0000x reference)
#include <cuda_runtime.h>
#include <math.h>

#define BN 2048
#define DN 3072
#define CN 10
#define MN 9

#define ALPHA  0.999999f             // 1 - C*NUM_STAB
#define NST    1e-7f
#define RS10   0.31622776601683794f  // 1/sqrt(10)

typedef unsigned long long u64;

// packed fp32x2 FMA: acc.{lo,hi} += a.{lo,hi} * b.{lo,hi}
#define FMA_X2(acc, a, b) \
    asm("fma.rn.f32x2 %0, %1, %2, %0;" : "+l"(acc) : "l"(a), "l"(b))
#define UNPACK_X2(lo, hi, v) \
    asm("mov.b64 {%0, %1}, %2;" : "=f"(lo), "=f"(hi) : "l"(v))

// Scratch (no allocations allowed)
__device__ __align__(16) float g_Wt[CN * DN];   // W transposed [C][D]
__device__ float g_Wg[CN * CN];                 // W^T W

// ---------------------------------------------------------------------------
// Prep: blocks 0..11 transpose W -> Wt (one d-row per thread, coalesced
//       writes per class); blocks 12..21 compute Wg rows.
// ---------------------------------------------------------------------------
__global__ void __launch_bounds__(256) prep_kernel(const float* __restrict__ W) {
    int bid = blockIdx.x;
    int tid = threadIdx.x;
    if (bid < 12) {
        int d = bid * 256 + tid;             // 0..3071
        float w[CN];
        #pragma unroll
        for (int c = 0; c < CN; c++) w[c] = __ldg(&W[d * CN + c]);
        #pragma unroll
        for (int c = 0; c < CN; c++) g_Wt[c * DN + d] = w[c];
    } else {
        int i = bid - 12;                    // Wg row i
        float acc[CN];
        #pragma unroll
        for (int j = 0; j < CN; j++) acc[j] = 0.f;
        for (int d = tid; d < DN; d += 256) {
            float w[CN];
            #pragma unroll
            for (int j = 0; j < CN; j++) w[j] = __ldg(&W[d * CN + j]);
            float wi = w[i];
            #pragma unroll
            for (int j = 0; j < CN; j++) acc[j] = fmaf(wi, w[j], acc[j]);
        }
        #pragma unroll
        for (int j = 0; j < CN; j++) {
            #pragma unroll
            for (int off = 16; off > 0; off >>= 1)
                acc[j] += __shfl_xor_sync(0xffffffffu, acc[j], off);
        }
        __shared__ float smem[8][CN];
        int w_ = tid >> 5, l = tid & 31;
        if (l == 0) {
            #pragma unroll
            for (int j = 0; j < CN; j++) smem[w_][j] = acc[j];
        }
        __syncthreads();
        if (tid < CN) {
            float s = 0.f;
            #pragma unroll
            for (int k = 0; k < 8; k++) s += smem[k][tid];
            g_Wg[i * CN + tid] = s;
        }
    }
}

// ---------------------------------------------------------------------------
// Fused main kernel: logits GEMM (FFMA2-packed) + per-sample epilogue.
// Grid: 128 blocks x 512 threads. Block = 16 samples.
// wid = octet(1b)|kidx(3b): kidx selects K-eighth (384 floats), octet selects
// 8-sample half. lane = pgrp(2b)|klane(3b): pgrp = sample pair, klane = K
// split within chunk. Each lane: 2 samples x 10 classes, accumulated as
// fp32x2 pairs over (even k, odd k).
// ---------------------------------------------------------------------------
__global__ void __launch_bounds__(512) main_kernel(const float* __restrict__ data,
                                                   const float* __restrict__ bias,
                                                   float* __restrict__ out) {
    __shared__ float sm[8][16][CN];          // [kidx][local sample][class]

    const int tid   = threadIdx.x;
    const int wid   = tid >> 5;
    const int lane  = tid & 31;
    const int kidx  = wid & 7;               // K-eighth
    const int octet = wid >> 3;              // sample half (0/1)
    const int pgrp  = lane >> 3;             // sample pair within half
    const int klane = lane & 7;

    const int ls  = octet * 8 + pgrp * 2;    // local sample (pair base)
    const int s0  = blockIdx.x * 16 + ls;

    const char* xb0 = reinterpret_cast<const char*>(data) + (size_t)s0 * (DN * 4);
    const char* xb1 = xb0 + DN * 4;
    const ulonglong2* __restrict__ wt = reinterpret_cast<const ulonglong2*>(g_Wt);

    u64 a0[CN], a1[CN];
    #pragma unroll
    for (int c = 0; c < CN; c++) { a0[c] = 0ull; a1[c] = 0ull; }

    const int kbase = kidx * 96 + klane;     // float4 index; chunk = 96 float4

    #pragma unroll 2
    for (int i = 0; i < 12; i++) {
        int k4 = kbase + i * 8;
        u64 x0lo, x0hi, x1lo, x1hi;
        // streaming loads: x read exactly once, keep L1 for W
        asm("ld.global.cs.v2.u64 {%0, %1}, [%2];"
            : "=l"(x0lo), "=l"(x0hi) : "l"(xb0 + (size_t)k4 * 16));
        asm("ld.global.cs.v2.u64 {%0, %1}, [%2];"
            : "=l"(x1lo), "=l"(x1hi) : "l"(xb1 + (size_t)k4 * 16));
        #pragma unroll
        for (int c = 0; c < CN; c++) {
            ulonglong2 wv = __ldg(&wt[c * 768 + k4]);
            FMA_X2(a0[c], x0lo, wv.x);
            FMA_X2(a0[c], x0hi, wv.y);
            FMA_X2(a1[c], x1lo, wv.x);
            FMA_X2(a1[c], x1hi, wv.y);
        }
    }

    // unpack pairs, then reduce across the 8 klanes (xor 1,2,4)
    float f0[CN], f1[CN];
    #pragma unroll
    for (int c = 0; c < CN; c++) {
        float lo, hi;
        UNPACK_X2(lo, hi, a0[c]); f0[c] = lo + hi;
        UNPACK_X2(lo, hi, a1[c]); f1[c] = lo + hi;
    }
    #pragma unroll
    for (int c = 0; c < CN; c++) {
        #pragma unroll
        for (int off = 4; off > 0; off >>= 1) {
            f0[c] += __shfl_xor_sync(0xffffffffu, f0[c], off);
            f1[c] += __shfl_xor_sync(0xffffffffu, f1[c], off);
        }
    }

    if (klane == 0) {
        #pragma unroll
        for (int c = 0; c < CN; c++) {
            sm[kidx][ls][c]     = f0[c];
            sm[kidx][ls + 1][c] = f1[c];
        }
    }
    __syncthreads();

    // ---------------- fused epilogue: 16 threads, one per sample -----------
    if (tid < 16) {
        float l[CN];
        #pragma unroll
        for (int c = 0; c < CN; c++) {
            float a = bias[c];
            #pragma unroll
            for (int k = 0; k < 8; k++) a += sm[k][tid][c];
            l[c] = a;
        }

        float mx = l[0];
        #pragma unroll
        for (int c = 1; c < CN; c++) mx = fmaxf(mx, l[c]);

        float e[CN], Z = 0.f;
        #pragma unroll
        for (int c = 0; c < CN; c++) { e[c] = expf(l[c] - mx); Z += e[c]; }
        float invZ = 1.f / Z;

        float s[CN], r[CN], sumr = 0.f;
        #pragma unroll
        for (int c = 0; c < CN; c++) {
            s[c] = e[c] * invZ;
            float p = fmaf(s[c], ALPHA, NST);
            r[c] = sqrtf(p);
            sumr += r[c];
        }
        float u = 1.f - r[MN];
        float delta = 2.f * acosf(fminf(sumr * RS10, 1.f));

        float wg[CN * CN];
        #pragma unroll
        for (int v = 0; v < CN * CN; v++) wg[v] = __ldg(&g_Wg[v]);

        float q[CN];
        #pragma unroll
        for (int j = 0; j < CN; j++) {
            float a = 0.f;
            #pragma unroll
            for (int k = 0; k < CN; k++) a = fmaf(s[k], wg[k * CN + j], a);
            q[j] = a;
        }
        float qs = 0.f;
        #pragma unroll
        for (int j = 0; j < CN; j++) qs = fmaf(q[j], s[j], qs);

        float inv_u = 1.f / u;
        float c2com = ALPHA * s[MN] * inv_u * inv_u / r[MN];
        float c1[MN], c2[MN], t[MN];
        #pragma unroll
        for (int m = 0; m < MN; m++) {
            c1[m] = ALPHA * s[m] * inv_u / r[m];
            c2[m] = c2com * r[m];
            t[m]  = c1[m] + c2[m];
        }

        float col[MN];
        #pragma unroll
        for (int n = 0; n < MN; n++) col[n] = 0.f;
        float norminf = 0.f;

        #pragma unroll
        for (int m = 0; m < MN; m++) {
            float Mrow[CN];
            #pragma unroll
            for (int j = 0; j < CN; j++)
                Mrow[j] = c1[m] * wg[m * CN + j] + c2[m] * wg[MN * CN + j] - t[m] * q[j];
            float wm = c1[m] * q[m] + c2[m] * q[MN] - t[m] * qs;
            float rowsum = 0.f;
            #pragma unroll
            for (int n = 0; n < MN; n++) {
                float g  = c1[n] * Mrow[n] + c2[n] * Mrow[MN] - t[n] * wm;
                float ag = fabsf(g);
                rowsum += ag;
                col[n] += ag;
            }
            norminf = fmaxf(norminf, rowsum);
        }
        float norm1 = 0.f;
        #pragma unroll
        for (int n = 0; n < MN; n++) norm1 = fmaxf(norm1, col[n]);

        float u2 = u * u;
        float jn = u2 * sqrtf(norm1 * norminf);
        out[blockIdx.x * 16 + tid] = delta / (0.1f * jn);
    }
}

// ---------------------------------------------------------------------------
extern "C" void kernel_launch(void* const* d_in, const int* in_sizes, int n_in,
                              void* d_out, int out_size) {
    const float* data = (const float*)d_in[0];   // [2048,3,32,32]
    const float* W    = (const float*)d_in[1];   // [3072,10]
    const float* bias = (const float*)d_in[2];   // [10]
    float* out = (float*)d_out;                  // [2048,1]

    prep_kernel<<<22, 256>>>(W);
    main_kernel<<<128, 512>>>(data, bias, out);
}

// round 5
// speedup vs baseline: 1.0017x; 1.0017x over previous
#include <cuda_runtime.h>
#include <cstdint>
#include <math.h>

#define BN 2048
#define DN 3072
#define CN 10
#define MN 9

#define ALPHA  0.999999f             // 1 - C*NUM_STAB
#define NST    1e-7f
#define RS10   0.31622776601683794f  // 1/sqrt(10)

typedef unsigned long long u64;
typedef unsigned int u32;

// packed fp32x2 FMA: acc.{lo,hi} += a.{lo,hi} * b.{lo,hi}
#define FMA_X2(acc, a, b) \
    asm("fma.rn.f32x2 %0, %1, %2, %0;" : "+l"(acc) : "l"(a), "l"(b))
#define UNPACK_X2(lo, hi, v) \
    asm("mov.b64 {%0, %1}, %2;" : "=f"(lo), "=f"(hi) : "l"(v))

#define CP_ASYNC16(dst, src) \
    asm volatile("cp.async.cg.shared.global [%0], [%1], 16;" :: "r"(dst), "l"(src))
#define CP_COMMIT() asm volatile("cp.async.commit_group;")
#define CP_WAIT(n)  asm volatile("cp.async.wait_group %0;" :: "n"(n))

// Scratch (no allocations allowed)
__device__ __align__(16) float g_Wt[CN * DN];   // W transposed [C][D]
__device__ float g_Wg[CN * CN];                 // W^T W

// ---------------------------------------------------------------------------
// Prep: blocks 0..11 transpose W -> Wt; blocks 12..21 compute Wg rows.
// ---------------------------------------------------------------------------
__global__ void __launch_bounds__(256) prep_kernel(const float* __restrict__ W) {
    int bid = blockIdx.x;
    int tid = threadIdx.x;
    if (bid < 12) {
        int d = bid * 256 + tid;             // 0..3071
        float w[CN];
        #pragma unroll
        for (int c = 0; c < CN; c++) w[c] = __ldg(&W[d * CN + c]);
        #pragma unroll
        for (int c = 0; c < CN; c++) g_Wt[c * DN + d] = w[c];
    } else {
        int i = bid - 12;                    // Wg row i
        float acc[CN];
        #pragma unroll
        for (int j = 0; j < CN; j++) acc[j] = 0.f;
        for (int d = tid; d < DN; d += 256) {
            float w[CN];
            #pragma unroll
            for (int j = 0; j < CN; j++) w[j] = __ldg(&W[d * CN + j]);
            float wi = w[i];
            #pragma unroll
            for (int j = 0; j < CN; j++) acc[j] = fmaf(wi, w[j], acc[j]);
        }
        #pragma unroll
        for (int j = 0; j < CN; j++) {
            #pragma unroll
            for (int off = 16; off > 0; off >>= 1)
                acc[j] += __shfl_xor_sync(0xffffffffu, acc[j], off);
        }
        __shared__ float smem[8][CN];
        int w_ = tid >> 5, l = tid & 31;
        if (l == 0) {
            #pragma unroll
            for (int j = 0; j < CN; j++) smem[w_][j] = acc[j];
        }
        __syncthreads();
        if (tid < CN) {
            float s = 0.f;
            #pragma unroll
            for (int k = 0; k < 8; k++) s += smem[k][tid];
            g_Wg[i * CN + tid] = s;
        }
    }
}

// ---------------------------------------------------------------------------
// Fused main kernel with cp.async staging.
// Grid: 128 blocks x 512 threads. Block = 16 samples.
// wid = octet(1b)|kidx(3b); lane = pgrp(2b)|klane(3b).
// Each warp owns a private 12KB SMEM slice: [4 pgrp][2 samples][96 float4]
// covering its 8 samples x K-eighth. Producer: 24 cp.async/lane in 3 groups.
// Consumer: per-thread wait_group (each lane reads only what it wrote).
// ---------------------------------------------------------------------------
extern __shared__ ulonglong2 xs[];   // [16 warps][4 pgrp][2 smp][96] = 192 KB

__global__ void __launch_bounds__(512, 1) main_kernel(const float* __restrict__ data,
                                                      const float* __restrict__ bias,
                                                      float* __restrict__ out) {
    __shared__ float sm[8][16][CN];          // [kidx][local sample][class]

    const int tid   = threadIdx.x;
    const int wid   = tid >> 5;
    const int lane  = tid & 31;
    const int kidx  = wid & 7;               // K-eighth (384 floats)
    const int octet = wid >> 3;              // sample half
    const int pgrp  = lane >> 3;             // sample pair within half
    const int klane = lane & 7;

    const int ls = octet * 8 + pgrp * 2;     // local sample (pair base)
    const int s0 = blockIdx.x * 16 + ls;

    // this lane's pgrp region: [2 samples][96 float4]
    ulonglong2* xw = xs + ((wid * 4 + pgrp) * 2) * 96;
    const u32 xw_addr = (u32)__cvta_generic_to_shared(xw);

    const float4* __restrict__ xg = reinterpret_cast<const float4*>(data);
    const size_t src0 = (size_t)s0 * 768 + kidx * 96;   // float4 idx, sample 0

    // ---------------- producer: 3 commit groups of 8 cp.async each ---------
    #pragma unroll
    for (int g = 0; g < 3; g++) {
        #pragma unroll
        for (int j = 0; j < 4; j++) {
            int k4l = (g * 4 + j) * 8 + klane;
            CP_ASYNC16(xw_addr + k4l * 16,         xg + src0 + k4l);
            CP_ASYNC16(xw_addr + (96 + k4l) * 16,  xg + src0 + 768 + k4l);
        }
        CP_COMMIT();
    }

    // ---------------- consumer: pipelined FFMA2 from SMEM ------------------
    u64 a0[CN], a1[CN];
    #pragma unroll
    for (int c = 0; c < CN; c++) { a0[c] = 0ull; a1[c] = 0ull; }

    const ulonglong2* __restrict__ wt = reinterpret_cast<const ulonglong2*>(g_Wt);
    const int kw = kidx * 96 + klane;        // W float4 index base

    #pragma unroll
    for (int g = 0; g < 3; g++) {
        if (g == 0) CP_WAIT(2);
        else if (g == 1) CP_WAIT(1);
        else CP_WAIT(0);
        #pragma unroll
        for (int ii = 0; ii < 4; ii++) {
            int i = g * 4 + ii;
            int k4l = i * 8 + klane;
            ulonglong2 xv0 = xw[k4l];
            ulonglong2 xv1 = xw[96 + k4l];
            #pragma unroll
            for (int c = 0; c < CN; c++) {
                ulonglong2 wv = __ldg(&wt[c * 768 + kw + i * 8]);
                FMA_X2(a0[c], xv0.x, wv.x);
                FMA_X2(a0[c], xv0.y, wv.y);
                FMA_X2(a1[c], xv1.x, wv.x);
                FMA_X2(a1[c], xv1.y, wv.y);
            }
        }
    }

    // unpack pairs, reduce across 8 klanes (xor 1,2,4 stay within pgrp)
    float f0[CN], f1[CN];
    #pragma unroll
    for (int c = 0; c < CN; c++) {
        float lo, hi;
        UNPACK_X2(lo, hi, a0[c]); f0[c] = lo + hi;
        UNPACK_X2(lo, hi, a1[c]); f1[c] = lo + hi;
    }
    #pragma unroll
    for (int c = 0; c < CN; c++) {
        #pragma unroll
        for (int off = 4; off > 0; off >>= 1) {
            f0[c] += __shfl_xor_sync(0xffffffffu, f0[c], off);
            f1[c] += __shfl_xor_sync(0xffffffffu, f1[c], off);
        }
    }

    if (klane == 0) {
        #pragma unroll
        for (int c = 0; c < CN; c++) {
            sm[kidx][ls][c]     = f0[c];
            sm[kidx][ls + 1][c] = f1[c];
        }
    }
    __syncthreads();

    // ---------------- fused epilogue: 16 threads, one per sample -----------
    if (tid < 16) {
        float l[CN];
        #pragma unroll
        for (int c = 0; c < CN; c++) {
            float a = bias[c];
            #pragma unroll
            for (int k = 0; k < 8; k++) a += sm[k][tid][c];
            l[c] = a;
        }

        float mx = l[0];
        #pragma unroll
        for (int c = 1; c < CN; c++) mx = fmaxf(mx, l[c]);

        float e[CN], Z = 0.f;
        #pragma unroll
        for (int c = 0; c < CN; c++) { e[c] = expf(l[c] - mx); Z += e[c]; }
        float invZ = 1.f / Z;

        float s[CN], r[CN], sumr = 0.f;
        #pragma unroll
        for (int c = 0; c < CN; c++) {
            s[c] = e[c] * invZ;
            float p = fmaf(s[c], ALPHA, NST);
            r[c] = sqrtf(p);
            sumr += r[c];
        }
        float u = 1.f - r[MN];
        float delta = 2.f * acosf(fminf(sumr * RS10, 1.f));

        float wg[CN * CN];
        #pragma unroll
        for (int v = 0; v < CN * CN; v++) wg[v] = __ldg(&g_Wg[v]);

        float q[CN];
        #pragma unroll
        for (int j = 0; j < CN; j++) {
            float a = 0.f;
            #pragma unroll
            for (int k = 0; k < CN; k++) a = fmaf(s[k], wg[k * CN + j], a);
            q[j] = a;
        }
        float qs = 0.f;
        #pragma unroll
        for (int j = 0; j < CN; j++) qs = fmaf(q[j], s[j], qs);

        float inv_u = 1.f / u;
        float c2com = ALPHA * s[MN] * inv_u * inv_u / r[MN];
        float c1[MN], c2[MN], t[MN];
        #pragma unroll
        for (int m = 0; m < MN; m++) {
            c1[m] = ALPHA * s[m] * inv_u / r[m];
            c2[m] = c2com * r[m];
            t[m]  = c1[m] + c2[m];
        }

        float col[MN];
        #pragma unroll
        for (int n = 0; n < MN; n++) col[n] = 0.f;
        float norminf = 0.f;

        #pragma unroll
        for (int m = 0; m < MN; m++) {
            float Mrow[CN];
            #pragma unroll
            for (int j = 0; j < CN; j++)
                Mrow[j] = c1[m] * wg[m * CN + j] + c2[m] * wg[MN * CN + j] - t[m] * q[j];
            float wm = c1[m] * q[m] + c2[m] * q[MN] - t[m] * qs;
            float rowsum = 0.f;
            #pragma unroll
            for (int n = 0; n < MN; n++) {
                float g2  = c1[n] * Mrow[n] + c2[n] * Mrow[MN] - t[n] * wm;
                float ag = fabsf(g2);
                rowsum += ag;
                col[n] += ag;
            }
            norminf = fmaxf(norminf, rowsum);
        }
        float norm1 = 0.f;
        #pragma unroll
        for (int n = 0; n < MN; n++) norm1 = fmaxf(norm1, col[n]);

        float u2 = u * u;
        float jn = u2 * sqrtf(norm1 * norminf);
        out[blockIdx.x * 16 + tid] = delta / (0.1f * jn);
    }
}

// ---------------------------------------------------------------------------
extern "C" void kernel_launch(void* const* d_in, const int* in_sizes, int n_in,
                              void* d_out, int out_size) {
    const float* data = (const float*)d_in[0];   // [2048,3,32,32]
    const float* W    = (const float*)d_in[1];   // [3072,10]
    const float* bias = (const float*)d_in[2];   // [10]
    float* out = (float*)d_out;                  // [2048,1]

    static int configured = 0;
    if (!configured) {
        cudaFuncSetAttribute(main_kernel,
                             cudaFuncAttributeMaxDynamicSharedMemorySize,
                             196608);
        configured = 1;
    }

    prep_kernel<<<22, 256>>>(W);
    main_kernel<<<128, 512, 196608>>>(data, bias, out);
}